// round 13
// baseline (speedup 1.0000x reference)
#include <cuda_runtime.h>
#include <cuda_fp16.h>
#include <cstdint>

// ---------------------------------------------------------------------------
// IWHT3Layer, round 13: occupancy push — 3 CTAs/SM (85-reg budget).
//   CTA: 256 threads / 8 warps / 16 pixels x 64 k x 1 branch.
//   Warp w: m16 x n8 (k = 8w..8w+7), ALL 16 t in regs (acc[16][4] = the
//   irreducible 64-reg floor). Register diet vs round 12:
//     - no deep x prefetch (measured zero effect), x(t+1) loaded at window top
//     - B single-buffered, loaded in-window (L2 exposure hidden by 6 w/SMSP)
//     - epilogue u-butterfly IN PLACE over acc (no U[4][4] array)
//   Epilogue: in-place 2D WHT + bias + float2 stores.
//   wprep: coalesced-store repack (1 thread per dst U64), 192 blocks.
// ---------------------------------------------------------------------------

#define U32 unsigned int
#define U64 unsigned long long

static constexpr int PIXELS   = 12544;
static constexpr int PIX_CTA  = 16;
static constexpr int NBLK     = PIXELS / PIX_CTA;   // 784
static constexpr int T_STRIDE = PIXELS * 64;
static constexpr long long OPB = 16LL * 112 * 112 * 64;

static constexpr int A_PITCH  = 144;                 // conflict-free ldmatrix+STS
static constexpr int A_BUF    = 16 * A_PITCH;        // 2304 B per buffer

// B fragments: per (branch,t,nb,lane): 4 x U64 (kc 0..3) contiguous (32B)
__device__ __align__(16) U64 g_bfrag[3 * 16 * 8 * 32 * 4];   // 49152 u64

// ---------------- helpers ----------------
__device__ __forceinline__ U32 smem_u32(const void* p) {
    U32 a; asm("{ .reg .u64 t; cvta.to.shared.u64 t, %1; cvt.u32.u64 %0, t; }"
               : "=r"(a) : "l"(p)); return a;
}
__device__ __forceinline__ void ldm4(U32& a0, U32& a1, U32& a2, U32& a3, U32 addr) {
    asm volatile("ldmatrix.sync.aligned.m8n8.x4.shared.b16 {%0,%1,%2,%3}, [%4];"
                 : "=r"(a0), "=r"(a1), "=r"(a2), "=r"(a3) : "r"(addr));
}
__device__ __forceinline__ void mma16816(float* d, U32 a0, U32 a1, U32 a2, U32 a3,
                                         U32 b0, U32 b1) {
    asm volatile("mma.sync.aligned.m16n8k16.row.col.f32.f16.f16.f32 "
                 "{%0,%1,%2,%3}, {%4,%5,%6,%7}, {%8,%9}, {%0,%1,%2,%3};"
                 : "+f"(d[0]), "+f"(d[1]), "+f"(d[2]), "+f"(d[3])
                 : "r"(a0), "r"(a1), "r"(a2), "r"(a3), "r"(b0), "r"(b1));
}

// ---------------- prep: coalesced-store fragment repack ----------------
__global__ void wprep_kernel(const float* __restrict__ w1,
                             const float* __restrict__ w2,
                             const float* __restrict__ w3) {
    int gid = blockIdx.x * 256 + threadIdx.x;           // 0..49151
    int kc   = gid & 3;
    int lane = (gid >> 2) & 31;
    int nb   = (gid >> 7) & 7;
    int t    = (gid >> 10) & 15;
    int br   = gid >> 14;
    const float* w = (br == 0 ? w1 : (br == 1 ? w2 : w3)) + t * 4096;
    int k  = nb * 8 + (lane >> 2);
    int cb = kc * 16 + 2 * (lane & 3);
    __half h0 = __float2half(w[(cb)     * 64 + k]);
    __half h1 = __float2half(w[(cb + 1) * 64 + k]);
    __half h2 = __float2half(w[(cb + 8) * 64 + k]);
    __half h3 = __float2half(w[(cb + 9) * 64 + k]);
    U32 lo = ((U32)__half_as_ushort(h1) << 16) | __half_as_ushort(h0);
    U32 hi = ((U32)__half_as_ushort(h3) << 16) | __half_as_ushort(h2);
    g_bfrag[gid] = (U64)lo | ((U64)hi << 32);
}

// ---------------- main kernel ----------------
__global__ __launch_bounds__(256, 3)
void iwht_mma_kernel(const float* __restrict__ tr1, const float* __restrict__ tr2,
                     const float* __restrict__ tr3,
                     const float* __restrict__ b1, const float* __restrict__ b2,
                     const float* __restrict__ b3,
                     float* __restrict__ out) {
    __shared__ __align__(16) char asm_buf[2 * A_BUF];   // 4608 B

    const int tid  = threadIdx.x;
    const int lane = tid & 31;
    const int w    = tid >> 5;     // 0..7 -> n8 block (k outputs)

    const int branch = blockIdx.y;
    const float* tr   = (branch == 0 ? tr1 : (branch == 1 ? tr2 : tr3));
    const float* bias = (branch == 0 ? b1  : (branch == 1 ? b2  : b3));
    const int pix0 = blockIdx.x * PIX_CTA;

    // staging role: thread -> (row 0..15, 4 floats at cseg*4)
    const int crow = tid >> 4, cseg = tid & 15;
    const float* xrow = tr + (size_t)(pix0 + crow) * 64 + cseg * 4;

    auto cvtStore = [&](float4 a, int buf) {
        __half2 h0 = __floats2half2_rn(a.x, a.y);
        __half2 h1 = __floats2half2_rn(a.z, a.w);
        *(uint2*)(asm_buf + buf * A_BUF + crow * A_PITCH + cseg * 8) =
            make_uint2(*reinterpret_cast<U32*>(&h0), *reinterpret_cast<U32*>(&h1));
    };

    // B fragments: 32B contiguous per (t, warp, lane)
    const U64* gb = g_bfrag + (((size_t)branch * 16 * 8 + w) * 32 + lane) * 4;

    // prologue: stage t=0
    cvtStore(*(const float4*)xrow, 0);
    __syncthreads();

    const U32 sbase = smem_u32(asm_buf);
    const U32 arow0 = sbase + (U32)((lane & 15) * A_PITCH + (lane >> 4) * 16);

    float acc[16][4];
    #pragma unroll
    for (int t = 0; t < 16; t++)
        #pragma unroll
        for (int i = 0; i < 4; i++) acc[t][i] = 0.0f;

    #pragma unroll
    for (int t = 0; t < 16; t++) {
        // x(t+1): issued at window top, consumed at window bottom
        float4 pa;
        if (t < 15) pa = *(const float4*)(xrow + (size_t)(t + 1) * T_STRIDE);

        // B(t): L2-hot, single-buffered (exposure hidden by 6 warps/SMSP)
        U64 bb[4];
        {
            const uint4* p = (const uint4*)(gb + (size_t)t * 8 * 32 * 4);
            uint4 v0 = p[0], v1 = p[1];
            bb[0] = (U64)v0.x | ((U64)v0.y << 32);
            bb[1] = (U64)v0.z | ((U64)v0.w << 32);
            bb[2] = (U64)v1.x | ((U64)v1.y << 32);
            bb[3] = (U64)v1.z | ((U64)v1.w << 32);
        }

        // MMAs for t
        const U32 ab = arow0 + (U32)((t & 1) * A_BUF);
        #pragma unroll
        for (int kc = 0; kc < 4; kc++) {
            U32 a0, a1, a2, a3;
            ldm4(a0, a1, a2, a3, ab + kc * 32);
            mma16816(acc[t], a0, a1, a2, a3,
                     (U32)bb[kc], (U32)(bb[kc] >> 32));
        }

        if (t < 15) cvtStore(pa, (t + 1) & 1);
        __syncthreads();
    }

    // ---------------- epilogue: IN-PLACE 2D WHT + bias + stores -------------
    // u-stage in place: after this, acc[4p+v][i] = U[p][v][i]
    #pragma unroll
    for (int v = 0; v < 4; v++) {
        #pragma unroll
        for (int i = 0; i < 4; i++) {
            float a = acc[v][i], b = acc[4 + v][i];
            float c = acc[8 + v][i], d = acc[12 + v][i];
            float s0 = a + c, s1 = b + d, d0 = a - c, d1 = b - d;
            acc[v][i]      = s0 + s1;
            acc[4 + v][i]  = s0 - s1;
            acc[8 + v][i]  = d0 + d1;
            acc[12 + v][i] = d0 - d1;
        }
    }

    const int cl = lane & 3, rl = lane >> 2;
    float* outB = out + (size_t)branch * OPB;
    const int kst = w * 8 + cl * 2;
    const float2 bv = *(const float2*)(bias + kst);

    #pragma unroll
    for (int rh = 0; rh < 2; rh++) {
        const int P = pix0 + rh * 8 + rl;
        const int pb_ = P / 784, rr = P - pb_ * 784;
        const int ii = rr / 28, jj = rr - ii * 28;
        float* obase = outB + ((size_t)(pb_ * 112 + ii * 4) * 112 + jj * 4) * 64 + kst;

        #pragma unroll
        for (int p = 0; p < 4; p++) {
            // v-stage from acc[4p+v][rh*2 + {0,1}]
            float s0x = acc[4*p+0][rh*2]   + acc[4*p+2][rh*2];
            float s0y = acc[4*p+0][rh*2+1] + acc[4*p+2][rh*2+1];
            float s1x = acc[4*p+1][rh*2]   + acc[4*p+3][rh*2];
            float s1y = acc[4*p+1][rh*2+1] + acc[4*p+3][rh*2+1];
            float d0x = acc[4*p+0][rh*2]   - acc[4*p+2][rh*2];
            float d0y = acc[4*p+0][rh*2+1] - acc[4*p+2][rh*2+1];
            float d1x = acc[4*p+1][rh*2]   - acc[4*p+3][rh*2];
            float d1y = acc[4*p+1][rh*2+1] - acc[4*p+3][rh*2+1];
            float zx[4], zy[4];
            zx[0] = s0x + s1x; zy[0] = s0y + s1y;
            zx[1] = s0x - s1x; zy[1] = s0y - s1y;
            zx[2] = d0x + d1x; zy[2] = d0y + d1y;
            zx[3] = d0x - d1x; zy[3] = d0y - d1y;
            float* orow = obase + (size_t)p * 7168;      // 112*64
            #pragma unroll
            for (int q = 0; q < 4; q++) {
                float ox = fmaf(zx[q], 0.0625f, bv.x);
                float oy = fmaf(zy[q], 0.0625f, bv.y);
                *(float2*)(orow + q * 64) = make_float2(ox, oy);
            }
        }
    }
}

// ---------------- launch ----------------
extern "C" void kernel_launch(void* const* d_in, const int* in_sizes, int n_in,
                              void* d_out, int out_size) {
    (void)in_sizes; (void)n_in; (void)out_size;
    const float* tr1 = (const float*)d_in[0];
    const float* tr2 = (const float*)d_in[1];
    const float* tr3 = (const float*)d_in[2];
    const float* w1  = (const float*)d_in[3];
    const float* w2  = (const float*)d_in[4];
    const float* w3  = (const float*)d_in[5];
    const float* b1  = (const float*)d_in[6];
    const float* b2  = (const float*)d_in[7];
    const float* b3  = (const float*)d_in[8];
    float* out = (float*)d_out;

    wprep_kernel<<<192, 256>>>(w1, w2, w3);
    dim3 grid(NBLK, 3);
    iwht_mma_kernel<<<grid, 256>>>(tr1, tr2, tr3, b1, b2, b3, out);
}

// round 14
// speedup vs baseline: 1.1905x; 1.1905x over previous
#include <cuda_runtime.h>
#include <cuda_fp16.h>
#include <cstdint>

// ---------------------------------------------------------------------------
// IWHT3Layer, round 14: v-split warps + pipelined u-group windows.
//   CTA: 256 threads / 8 warps / 16 pixels x 64 k x 1 branch, 2 CTAs/SM.
//   Warp (v=w&3, h=w>>2): processes t=4u+v for u=0..3, n32 (k 32h..32h+31).
//   4 windows (u): stage t=4u..4u+3 (double-buffered 4-t slots), barrier,
//   each warp: 4 ldmatrix (its t only -> 4x less LDSM than round 8) + 16 MMA.
//   x prefetch: 4 LDG.128/thread issued a full window (~800cyc) ahead.
//   Epilogue (round 10): u-butterfly in regs; U exchanged via smem in 2
//   p-passes; v-butterfly + bias; contiguous per-pixel-row float2 stores
//   (2 wf/STG instead of 8).
// ---------------------------------------------------------------------------

#define U32 unsigned int
#define U64 unsigned long long

static constexpr int PIXELS   = 12544;
static constexpr int PIX_CTA  = 16;
static constexpr int NBLK     = PIXELS / PIX_CTA;   // 784
static constexpr int T_STRIDE = PIXELS * 64;
static constexpr long long OPB = 16LL * 112 * 112 * 64;

static constexpr int A_PITCH  = 144;                 // conflict-free ldmatrix+STS
static constexpr int A_BUF    = 16 * A_PITCH;        // 2304 B per t-slot
// staging: 8 slots (2 windows x 4 t) = 18432 B
static constexpr int U_PITCH  = 68;                  // floats
static constexpr int SMEM_SZ  = 8 * 16 * U_PITCH * 4;  // 34816 B (>= 18432)

// B fragments: per (branch,t,nb,lane): 4 x U64 (kc 0..3) contiguous (32B)
__device__ __align__(16) U64 g_bfrag[3 * 16 * 8 * 32 * 4];   // 49152 u64

// ---------------- helpers ----------------
__device__ __forceinline__ U32 smem_u32(const void* p) {
    U32 a; asm("{ .reg .u64 t; cvta.to.shared.u64 t, %1; cvt.u32.u64 %0, t; }"
               : "=r"(a) : "l"(p)); return a;
}
__device__ __forceinline__ void ldm4(U32& a0, U32& a1, U32& a2, U32& a3, U32 addr) {
    asm volatile("ldmatrix.sync.aligned.m8n8.x4.shared.b16 {%0,%1,%2,%3}, [%4];"
                 : "=r"(a0), "=r"(a1), "=r"(a2), "=r"(a3) : "r"(addr));
}
__device__ __forceinline__ void mma16816(float* d, U32 a0, U32 a1, U32 a2, U32 a3,
                                         U32 b0, U32 b1) {
    asm volatile("mma.sync.aligned.m16n8k16.row.col.f32.f16.f16.f32 "
                 "{%0,%1,%2,%3}, {%4,%5,%6,%7}, {%8,%9}, {%0,%1,%2,%3};"
                 : "+f"(d[0]), "+f"(d[1]), "+f"(d[2]), "+f"(d[3])
                 : "r"(a0), "r"(a1), "r"(a2), "r"(a3), "r"(b0), "r"(b1));
}

// ---------------- prep: coalesced-store fragment repack ----------------
__global__ void wprep_kernel(const float* __restrict__ w1,
                             const float* __restrict__ w2,
                             const float* __restrict__ w3) {
    int gid = blockIdx.x * 256 + threadIdx.x;           // 0..49151
    int kc   = gid & 3;
    int lane = (gid >> 2) & 31;
    int nb   = (gid >> 7) & 7;
    int t    = (gid >> 10) & 15;
    int br   = gid >> 14;
    const float* w = (br == 0 ? w1 : (br == 1 ? w2 : w3)) + t * 4096;
    int k  = nb * 8 + (lane >> 2);
    int cb = kc * 16 + 2 * (lane & 3);
    __half h0 = __float2half(w[(cb)     * 64 + k]);
    __half h1 = __float2half(w[(cb + 1) * 64 + k]);
    __half h2 = __float2half(w[(cb + 8) * 64 + k]);
    __half h3 = __float2half(w[(cb + 9) * 64 + k]);
    U32 lo = ((U32)__half_as_ushort(h1) << 16) | __half_as_ushort(h0);
    U32 hi = ((U32)__half_as_ushort(h3) << 16) | __half_as_ushort(h2);
    g_bfrag[gid] = (U64)lo | ((U64)hi << 32);
}

// ---------------- main kernel ----------------
__global__ __launch_bounds__(256, 2)
void iwht_mma_kernel(const float* __restrict__ tr1, const float* __restrict__ tr2,
                     const float* __restrict__ tr3,
                     const float* __restrict__ b1, const float* __restrict__ b2,
                     const float* __restrict__ b3,
                     float* __restrict__ out) {
    __shared__ __align__(16) char asm_buf[SMEM_SZ];
    float* const ubuf = (float*)asm_buf;              // epilogue overlay

    const int tid  = threadIdx.x;
    const int lane = tid & 31;
    const int w    = tid >> 5;     // 0..7
    const int v    = w & 3;        // WHT column group
    const int h    = w >> 2;       // n-half (k 0..31 / 32..63)

    const int branch = blockIdx.y;
    const float* tr   = (branch == 0 ? tr1 : (branch == 1 ? tr2 : tr3));
    const float* bias = (branch == 0 ? b1  : (branch == 1 ? b2  : b3));
    const int pix0 = blockIdx.x * PIX_CTA;

    // staging role: thread -> (row 0..15, 4 floats at cseg*4)
    const int crow = tid >> 4, cseg = tid & 15;
    const float* xrow = tr + (size_t)(pix0 + crow) * 64 + cseg * 4;

    auto cvtStore = [&](float4 a, int slot) {
        __half2 h0 = __floats2half2_rn(a.x, a.y);
        __half2 h1 = __floats2half2_rn(a.z, a.w);
        *(uint2*)(asm_buf + slot * A_BUF + crow * A_PITCH + cseg * 8) =
            make_uint2(*reinterpret_cast<U32*>(&h0), *reinterpret_cast<U32*>(&h1));
    };

    // prologue: stage window 0 (t = 0..3)
    {
        float4 va[4];
        #pragma unroll
        for (int j = 0; j < 4; j++)
            va[j] = *(const float4*)(xrow + (size_t)j * T_STRIDE);
        #pragma unroll
        for (int j = 0; j < 4; j++) cvtStore(va[j], j);
    }
    __syncthreads();

    const U32 sbase = smem_u32(asm_buf);
    const U32 arow0 = sbase + (U32)((lane & 15) * A_PITCH + (lane >> 4) * 16);
    const U64* gbase = g_bfrag + (size_t)branch * 16 * 8 * 32 * 4;

    float acc[4][4][4];            // [u][nbq][i] -- all STATIC indexing
    #pragma unroll
    for (int u = 0; u < 4; u++)
        #pragma unroll
        for (int n = 0; n < 4; n++)
            #pragma unroll
            for (int i = 0; i < 4; i++) acc[u][n][i] = 0.0f;

    #pragma unroll
    for (int u = 0; u < 4; u++) {
        // prefetch next window's x (full window of slack)
        float4 pa[4];
        if (u < 3) {
            #pragma unroll
            for (int j = 0; j < 4; j++)
                pa[j] = *(const float4*)(xrow + (size_t)(4 * u + 4 + j) * T_STRIDE);
        }

        // this warp's t in this window
        const int t = 4 * u + v;
        const U32 ab = arow0 + (U32)(((u & 1) * 4 + v) * A_BUF);
        U32 af[4][4];
        #pragma unroll
        for (int kc = 0; kc < 4; kc++)
            ldm4(af[kc][0], af[kc][1], af[kc][2], af[kc][3], ab + kc * 32);

        #pragma unroll
        for (int nbq = 0; nbq < 4; nbq++) {
            const uint4* bp = (const uint4*)(gbase +
                (((size_t)t * 8 + h * 4 + nbq) * 32 + lane) * 4);
            uint4 bv0 = bp[0], bv1 = bp[1];
            U32 bb[8] = { bv0.x, bv0.y, bv0.z, bv0.w, bv1.x, bv1.y, bv1.z, bv1.w };
            #pragma unroll
            for (int kc = 0; kc < 4; kc++)
                mma16816(acc[u][nbq], af[kc][0], af[kc][1], af[kc][2], af[kc][3],
                         bb[kc * 2], bb[kc * 2 + 1]);
        }

        // stage next window
        if (u < 3) {
            #pragma unroll
            for (int j = 0; j < 4; j++)
                cvtStore(pa[j], ((u + 1) & 1) * 4 + j);
        }
        __syncthreads();
    }

    // ---------------- epilogue: 2-pass U exchange + v-butterfly ------------
    const int cl = lane & 3, rl = lane >> 2;
    float* const outB = out + (size_t)branch * OPB;
    const float2 bvv = *(const float2*)(bias + 2 * lane);

    // per-unit output addressing (pix = w + 8r, k = 2*lane)
    int opix[2]; size_t obase[2];
    #pragma unroll
    for (int r = 0; r < 2; r++) {
        const int pix = w + 8 * r;
        const int P = pix0 + pix;
        const int pb_ = P / 784, rr = P - pb_ * 784;
        const int ii = rr / 28, jj = rr - ii * 28;
        opix[r] = pix;
        obase[r] = ((size_t)(pb_ * 112 + ii * 4) * 112 + jj * 4) * 64 + 2 * lane;
    }

    #pragma unroll
    for (int pp = 0; pp < 2; pp++) {
        __syncthreads();    // pass 0: ldmatrix all done; pass 1: reads done

        // write planes (p = 2*pp + pl, this warp's v), u-butterfly in regs
        #pragma unroll
        for (int nbq = 0; nbq < 4; nbq++) {
            float Up[2][4];
            #pragma unroll
            for (int i = 0; i < 4; i++) {
                float y0 = acc[0][nbq][i], y1 = acc[1][nbq][i];
                float y2 = acc[2][nbq][i], y3 = acc[3][nbq][i];
                if (pp == 0) {
                    float s0 = y0 + y2, s1 = y1 + y3;
                    Up[0][i] = s0 + s1;      // p=0
                    Up[1][i] = s0 - s1;      // p=1
                } else {
                    float d0 = y0 - y2, d1 = y1 - y3;
                    Up[0][i] = d0 + d1;      // p=2
                    Up[1][i] = d0 - d1;      // p=3
                }
            }
            const int kcol = h * 32 + nbq * 8 + 2 * cl;
            #pragma unroll
            for (int pl = 0; pl < 2; pl++) {
                int base = ((pl * 4 + v) * 16 + rl) * U_PITCH + kcol;
                *(float2*)(ubuf + base)               = make_float2(Up[pl][0], Up[pl][1]);
                *(float2*)(ubuf + base + 8 * U_PITCH) = make_float2(Up[pl][2], Up[pl][3]);
            }
        }
        __syncthreads();

        // read + v-butterfly + store (unit: pix = w + 8r, k = 2*lane)
        #pragma unroll
        for (int r = 0; r < 2; r++) {
            #pragma unroll
            for (int pl = 0; pl < 2; pl++) {
                float2 Uv[4];
                #pragma unroll
                for (int vv = 0; vv < 4; vv++)
                    Uv[vv] = *(const float2*)(ubuf +
                        ((pl * 4 + vv) * 16 + opix[r]) * U_PITCH + 2 * lane);
                float2 s0 = make_float2(Uv[0].x + Uv[2].x, Uv[0].y + Uv[2].y);
                float2 s1 = make_float2(Uv[1].x + Uv[3].x, Uv[1].y + Uv[3].y);
                float2 d0 = make_float2(Uv[0].x - Uv[2].x, Uv[0].y - Uv[2].y);
                float2 d1 = make_float2(Uv[1].x - Uv[3].x, Uv[1].y - Uv[3].y);
                float2 Z[4];
                Z[0] = make_float2(s0.x + s1.x, s0.y + s1.y);
                Z[1] = make_float2(s0.x - s1.x, s0.y - s1.y);
                Z[2] = make_float2(d0.x + d1.x, d0.y + d1.y);
                Z[3] = make_float2(d0.x - d1.x, d0.y - d1.y);
                const int p = pp * 2 + pl;
                float* orow = outB + obase[r] + (size_t)p * 7168;   // p*112*64
                #pragma unroll
                for (int q = 0; q < 4; q++) {
                    float zx = fmaf(Z[q].x, 0.0625f, bvv.x);
                    float zy = fmaf(Z[q].y, 0.0625f, bvv.y);
                    *(float2*)(orow + q * 64) = make_float2(zx, zy);
                }
            }
        }
    }
}

// ---------------- launch ----------------
extern "C" void kernel_launch(void* const* d_in, const int* in_sizes, int n_in,
                              void* d_out, int out_size) {
    (void)in_sizes; (void)n_in; (void)out_size;
    const float* tr1 = (const float*)d_in[0];
    const float* tr2 = (const float*)d_in[1];
    const float* tr3 = (const float*)d_in[2];
    const float* w1  = (const float*)d_in[3];
    const float* w2  = (const float*)d_in[4];
    const float* w3  = (const float*)d_in[5];
    const float* b1  = (const float*)d_in[6];
    const float* b2  = (const float*)d_in[7];
    const float* b3  = (const float*)d_in[8];
    float* out = (float*)d_out;

    wprep_kernel<<<192, 256>>>(w1, w2, w3);
    dim3 grid(NBLK, 3);
    iwht_mma_kernel<<<grid, 256>>>(tr1, tr2, tr3, b1, b2, b3, out);
}

// round 15
// speedup vs baseline: 1.1945x; 1.0034x over previous
#include <cuda_runtime.h>
#include <cuda_fp16.h>
#include <cstdint>

// ---------------------------------------------------------------------------
// IWHT3Layer, round 15: round-14 mainloop + fragment-layout U exchange.
//   CTA: 256 threads / 8 warps / 16 pixels x 64 k x 1 branch, 2 CTAs/SM.
//   Warp (v=w&3, h=w>>2): t=4u+v, n32. Windowed staging (4 t / window).
//   Epilogue: u-butterfly in regs -> U stored in WRITER-NATURAL fragment
//   layout (STS.128, 4 wf) -> reader LDS.128 gathers k-pair for BOTH pixel
//   rows at once (nbq-padded stride 4160 -> 4-wf floor) -> v-butterfly +
//   bias -> contiguous float2 stores.
// ---------------------------------------------------------------------------

#define U32 unsigned int
#define U64 unsigned long long

static constexpr int PIXELS   = 12544;
static constexpr int PIX_CTA  = 16;
static constexpr int NBLK     = PIXELS / PIX_CTA;   // 784
static constexpr int T_STRIDE = PIXELS * 64;
static constexpr long long OPB = 16LL * 112 * 112 * 64;

static constexpr int A_PITCH  = 144;                 // conflict-free ldmatrix+STS
static constexpr int A_BUF    = 16 * A_PITCH;        // 2304 B per t-slot
// staging: 8 slots = 18432 B
static constexpr int NBQ_STRIDE = 4160;              // 8*32*16 + 64 pad
static constexpr int SMEM_SZ  = 8 * NBQ_STRIDE;      // 33280 B (>= 18432)

// B fragments: per (branch,t,nb,lane): 4 x U64 (kc 0..3) contiguous (32B)
__device__ __align__(16) U64 g_bfrag[3 * 16 * 8 * 32 * 4];   // 49152 u64

// ---------------- helpers ----------------
__device__ __forceinline__ U32 smem_u32(const void* p) {
    U32 a; asm("{ .reg .u64 t; cvta.to.shared.u64 t, %1; cvt.u32.u64 %0, t; }"
               : "=r"(a) : "l"(p)); return a;
}
__device__ __forceinline__ void ldm4(U32& a0, U32& a1, U32& a2, U32& a3, U32 addr) {
    asm volatile("ldmatrix.sync.aligned.m8n8.x4.shared.b16 {%0,%1,%2,%3}, [%4];"
                 : "=r"(a0), "=r"(a1), "=r"(a2), "=r"(a3) : "r"(addr));
}
__device__ __forceinline__ void mma16816(float* d, U32 a0, U32 a1, U32 a2, U32 a3,
                                         U32 b0, U32 b1) {
    asm volatile("mma.sync.aligned.m16n8k16.row.col.f32.f16.f16.f32 "
                 "{%0,%1,%2,%3}, {%4,%5,%6,%7}, {%8,%9}, {%0,%1,%2,%3};"
                 : "+f"(d[0]), "+f"(d[1]), "+f"(d[2]), "+f"(d[3])
                 : "r"(a0), "r"(a1), "r"(a2), "r"(a3), "r"(b0), "r"(b1));
}

// ---------------- prep: coalesced-store fragment repack ----------------
__global__ void wprep_kernel(const float* __restrict__ w1,
                             const float* __restrict__ w2,
                             const float* __restrict__ w3) {
    int gid = blockIdx.x * 256 + threadIdx.x;           // 0..49151
    int kc   = gid & 3;
    int lane = (gid >> 2) & 31;
    int nb   = (gid >> 7) & 7;
    int t    = (gid >> 10) & 15;
    int br   = gid >> 14;
    const float* w = (br == 0 ? w1 : (br == 1 ? w2 : w3)) + t * 4096;
    int k  = nb * 8 + (lane >> 2);
    int cb = kc * 16 + 2 * (lane & 3);
    __half h0 = __float2half(w[(cb)     * 64 + k]);
    __half h1 = __float2half(w[(cb + 1) * 64 + k]);
    __half h2 = __float2half(w[(cb + 8) * 64 + k]);
    __half h3 = __float2half(w[(cb + 9) * 64 + k]);
    U32 lo = ((U32)__half_as_ushort(h1) << 16) | __half_as_ushort(h0);
    U32 hi = ((U32)__half_as_ushort(h3) << 16) | __half_as_ushort(h2);
    g_bfrag[gid] = (U64)lo | ((U64)hi << 32);
}

// ---------------- main kernel ----------------
__global__ __launch_bounds__(256, 2)
void iwht_mma_kernel(const float* __restrict__ tr1, const float* __restrict__ tr2,
                     const float* __restrict__ tr3,
                     const float* __restrict__ b1, const float* __restrict__ b2,
                     const float* __restrict__ b3,
                     float* __restrict__ out) {
    __shared__ __align__(16) char asm_buf[SMEM_SZ];

    const int tid  = threadIdx.x;
    const int lane = tid & 31;
    const int w    = tid >> 5;     // 0..7
    const int v    = w & 3;        // WHT column group
    const int h    = w >> 2;       // n-half (k 0..31 / 32..63)

    const int branch = blockIdx.y;
    const float* tr   = (branch == 0 ? tr1 : (branch == 1 ? tr2 : tr3));
    const float* bias = (branch == 0 ? b1  : (branch == 1 ? b2  : b3));
    const int pix0 = blockIdx.x * PIX_CTA;

    // staging role: thread -> (row 0..15, 4 floats at cseg*4)
    const int crow = tid >> 4, cseg = tid & 15;
    const float* xrow = tr + (size_t)(pix0 + crow) * 64 + cseg * 4;

    auto cvtStore = [&](float4 a, int slot) {
        __half2 h0 = __floats2half2_rn(a.x, a.y);
        __half2 h1 = __floats2half2_rn(a.z, a.w);
        *(uint2*)(asm_buf + slot * A_BUF + crow * A_PITCH + cseg * 8) =
            make_uint2(*reinterpret_cast<U32*>(&h0), *reinterpret_cast<U32*>(&h1));
    };

    // prologue: stage window 0 (t = 0..3)
    {
        float4 va[4];
        #pragma unroll
        for (int j = 0; j < 4; j++)
            va[j] = *(const float4*)(xrow + (size_t)j * T_STRIDE);
        #pragma unroll
        for (int j = 0; j < 4; j++) cvtStore(va[j], j);
    }
    __syncthreads();

    const U32 sbase = smem_u32(asm_buf);
    const U32 arow0 = sbase + (U32)((lane & 15) * A_PITCH + (lane >> 4) * 16);
    const U64* gbase = g_bfrag + (size_t)branch * 16 * 8 * 32 * 4;

    float acc[4][4][4];            // [u][nbq][i] -- all STATIC indexing
    #pragma unroll
    for (int u = 0; u < 4; u++)
        #pragma unroll
        for (int n = 0; n < 4; n++)
            #pragma unroll
            for (int i = 0; i < 4; i++) acc[u][n][i] = 0.0f;

    #pragma unroll
    for (int u = 0; u < 4; u++) {
        // prefetch next window's x (full window of slack)
        float4 pa[4];
        if (u < 3) {
            #pragma unroll
            for (int j = 0; j < 4; j++)
                pa[j] = *(const float4*)(xrow + (size_t)(4 * u + 4 + j) * T_STRIDE);
        }

        // this warp's t in this window
        const int t = 4 * u + v;
        const U32 ab = arow0 + (U32)(((u & 1) * 4 + v) * A_BUF);
        U32 af[4][4];
        #pragma unroll
        for (int kc = 0; kc < 4; kc++)
            ldm4(af[kc][0], af[kc][1], af[kc][2], af[kc][3], ab + kc * 32);

        #pragma unroll
        for (int nbq = 0; nbq < 4; nbq++) {
            const uint4* bp = (const uint4*)(gbase +
                (((size_t)t * 8 + h * 4 + nbq) * 32 + lane) * 4);
            uint4 bv0 = bp[0], bv1 = bp[1];
            U32 bb[8] = { bv0.x, bv0.y, bv0.z, bv0.w, bv1.x, bv1.y, bv1.z, bv1.w };
            #pragma unroll
            for (int kc = 0; kc < 4; kc++)
                mma16816(acc[u][nbq], af[kc][0], af[kc][1], af[kc][2], af[kc][3],
                         bb[kc * 2], bb[kc * 2 + 1]);
        }

        // stage next window
        if (u < 3) {
            #pragma unroll
            for (int j = 0; j < 4; j++)
                cvtStore(pa[j], ((u + 1) & 1) * 4 + j);
        }
        __syncthreads();
    }

    // ---------------- epilogue: fragment-layout exchange ----------------
    // ubuf layout: [nbq_g 0..7 (stride 4160B)] [plane_slot 0..7][wlane 0..31] float4
    //   plane_slot = (p&1)*4 + v ; wlane = rl*4 + cl (writer lane)
    float* const outB = out + (size_t)branch * OPB;
    const float2 bvv = *(const float2*)(bias + 2 * lane);

    // output addressing (pix = w + 8r, k = 2*lane)
    size_t obase[2];
    #pragma unroll
    for (int r = 0; r < 2; r++) {
        const int P = pix0 + w + 8 * r;
        const int pb_ = P / 784, rr = P - pb_ * 784;
        const int ii = rr / 28, jj = rr - ii * 28;
        obase[r] = ((size_t)(pb_ * 112 + ii * 4) * 112 + jj * 4) * 64 + 2 * lane;
    }

    // reader base: nbq_g = lane>>2, gather lane = w*4 + (lane&3)
    const int rbase = (lane >> 2) * NBQ_STRIDE + (w * 4 + (lane & 3)) * 16;

    #pragma unroll
    for (int pp = 0; pp < 2; pp++) {
        __syncthreads();    // pass 0: A-reads done; pass 1: prior reads done

        // writer: u-butterfly in regs, STS.128 in fragment layout
        #pragma unroll
        for (int nbq = 0; nbq < 4; nbq++) {
            float Up[2][4];
            #pragma unroll
            for (int i = 0; i < 4; i++) {
                float y0 = acc[0][nbq][i], y1 = acc[1][nbq][i];
                float y2 = acc[2][nbq][i], y3 = acc[3][nbq][i];
                if (pp == 0) {
                    float s0 = y0 + y2, s1 = y1 + y3;
                    Up[0][i] = s0 + s1;      // p=0
                    Up[1][i] = s0 - s1;      // p=1
                } else {
                    float d0 = y0 - y2, d1 = y1 - y3;
                    Up[0][i] = d0 + d1;      // p=2
                    Up[1][i] = d0 - d1;      // p=3
                }
            }
            const int nbq_g = h * 4 + nbq;
            #pragma unroll
            for (int pl = 0; pl < 2; pl++) {
                *(float4*)(asm_buf + nbq_g * NBQ_STRIDE
                           + ((pl * 4 + v) * 32 + lane) * 16) =
                    make_float4(Up[pl][0], Up[pl][1], Up[pl][2], Up[pl][3]);
            }
        }
        __syncthreads();

        // reader: LDS.128 gathers (k,k+1) for BOTH pixel rows (w, w+8)
        #pragma unroll
        for (int pl = 0; pl < 2; pl++) {
            float4 Uv[4];
            #pragma unroll
            for (int vv = 0; vv < 4; vv++)
                Uv[vv] = *(const float4*)(asm_buf + rbase
                                          + ((pl * 4 + vv) * 32) * 16);
            // v-butterfly, componentwise (x,y = pix w ; z,w = pix w+8)
            float4 s0, s1, d0, d1, Z[4];
            s0.x = Uv[0].x + Uv[2].x; s0.y = Uv[0].y + Uv[2].y;
            s0.z = Uv[0].z + Uv[2].z; s0.w = Uv[0].w + Uv[2].w;
            s1.x = Uv[1].x + Uv[3].x; s1.y = Uv[1].y + Uv[3].y;
            s1.z = Uv[1].z + Uv[3].z; s1.w = Uv[1].w + Uv[3].w;
            d0.x = Uv[0].x - Uv[2].x; d0.y = Uv[0].y - Uv[2].y;
            d0.z = Uv[0].z - Uv[2].z; d0.w = Uv[0].w - Uv[2].w;
            d1.x = Uv[1].x - Uv[3].x; d1.y = Uv[1].y - Uv[3].y;
            d1.z = Uv[1].z - Uv[3].z; d1.w = Uv[1].w - Uv[3].w;
            Z[0].x = s0.x + s1.x; Z[0].y = s0.y + s1.y; Z[0].z = s0.z + s1.z; Z[0].w = s0.w + s1.w;
            Z[1].x = s0.x - s1.x; Z[1].y = s0.y - s1.y; Z[1].z = s0.z - s1.z; Z[1].w = s0.w - s1.w;
            Z[2].x = d0.x + d1.x; Z[2].y = d0.y + d1.y; Z[2].z = d0.z + d1.z; Z[2].w = d0.w + d1.w;
            Z[3].x = d0.x - d1.x; Z[3].y = d0.y - d1.y; Z[3].z = d0.z - d1.z; Z[3].w = d0.w - d1.w;

            const int p = pp * 2 + pl;
            float* orow0 = outB + obase[0] + (size_t)p * 7168;   // pix = w
            float* orow1 = outB + obase[1] + (size_t)p * 7168;   // pix = w+8
            #pragma unroll
            for (int q = 0; q < 4; q++) {
                *(float2*)(orow0 + q * 64) =
                    make_float2(fmaf(Z[q].x, 0.0625f, bvv.x),
                                fmaf(Z[q].y, 0.0625f, bvv.y));
                *(float2*)(orow1 + q * 64) =
                    make_float2(fmaf(Z[q].z, 0.0625f, bvv.x),
                                fmaf(Z[q].w, 0.0625f, bvv.y));
            }
        }
    }
}

// ---------------- launch ----------------
extern "C" void kernel_launch(void* const* d_in, const int* in_sizes, int n_in,
                              void* d_out, int out_size) {
    (void)in_sizes; (void)n_in; (void)out_size;
    const float* tr1 = (const float*)d_in[0];
    const float* tr2 = (const float*)d_in[1];
    const float* tr3 = (const float*)d_in[2];
    const float* w1  = (const float*)d_in[3];
    const float* w2  = (const float*)d_in[4];
    const float* w3  = (const float*)d_in[5];
    const float* b1  = (const float*)d_in[6];
    const float* b2  = (const float*)d_in[7];
    const float* b3  = (const float*)d_in[8];
    float* out = (float*)d_out;

    wprep_kernel<<<192, 256>>>(w1, w2, w3);
    dim3 grid(NBLK, 3);
    iwht_mma_kernel<<<grid, 256>>>(tr1, tr2, tr3, b1, b2, b3, out);
}

// round 16
// speedup vs baseline: 1.2460x; 1.0431x over previous
#include <cuda_runtime.h>
#include <cuda_fp16.h>
#include <cstdint>

// ---------------------------------------------------------------------------
// IWHT3Layer, round 16: round-15 + B ping-pong pipeline + 1-pass epilogue.
//   CTA: 256 threads / 8 warps / 16 pixels x 64 k x 1 branch, 2 CTAs/SM.
//   Warp (v=w&3, h=w>>2): t=4u+v, n32, acc[u][nbq][4] (static).
//   Mainloop: windowed staging (4 t / window, double-buffered); B loaded
//   one nbq ahead (bbuf[2][8] ping-pong) -> L2 latency hidden behind MMAs.
//   Epilogue: single pass — writer u-butterfly + all 4 planes to ubuf
//   (16x STS.128, fragment layout), ONE barrier, reader 16x LDS.128
//   (4x ILP) + v-butterfly + bias + contiguous float2 stores.
// ---------------------------------------------------------------------------

#define U32 unsigned int
#define U64 unsigned long long

static constexpr int PIXELS   = 12544;
static constexpr int PIX_CTA  = 16;
static constexpr int NBLK     = PIXELS / PIX_CTA;   // 784
static constexpr int T_STRIDE = PIXELS * 64;
static constexpr long long OPB = 16LL * 112 * 112 * 64;

static constexpr int A_PITCH  = 144;                 // conflict-free ldmatrix+STS
static constexpr int A_BUF    = 16 * A_PITCH;        // 2304 B per t-slot
// staging: 8 slots = 18432 B (overlaid on ubuf)
static constexpr int NBQ_STRIDE = 16 * 512 + 64;     // 8256 B (bank-rotating)
static constexpr int SMEM_SZ  = 8 * NBQ_STRIDE;      // 66048 B

// B fragments: per (branch,t,nb,lane): 4 x U64 (kc 0..3) contiguous (32B)
__device__ __align__(16) U64 g_bfrag[3 * 16 * 8 * 32 * 4];   // 49152 u64

// ---------------- helpers ----------------
__device__ __forceinline__ U32 smem_u32(const void* p) {
    U32 a; asm("{ .reg .u64 t; cvta.to.shared.u64 t, %1; cvt.u32.u64 %0, t; }"
               : "=r"(a) : "l"(p)); return a;
}
__device__ __forceinline__ void ldm4(U32& a0, U32& a1, U32& a2, U32& a3, U32 addr) {
    asm volatile("ldmatrix.sync.aligned.m8n8.x4.shared.b16 {%0,%1,%2,%3}, [%4];"
                 : "=r"(a0), "=r"(a1), "=r"(a2), "=r"(a3) : "r"(addr));
}
__device__ __forceinline__ void mma16816(float* d, U32 a0, U32 a1, U32 a2, U32 a3,
                                         U32 b0, U32 b1) {
    asm volatile("mma.sync.aligned.m16n8k16.row.col.f32.f16.f16.f32 "
                 "{%0,%1,%2,%3}, {%4,%5,%6,%7}, {%8,%9}, {%0,%1,%2,%3};"
                 : "+f"(d[0]), "+f"(d[1]), "+f"(d[2]), "+f"(d[3])
                 : "r"(a0), "r"(a1), "r"(a2), "r"(a3), "r"(b0), "r"(b1));
}

// ---------------- prep: coalesced-store fragment repack ----------------
__global__ void wprep_kernel(const float* __restrict__ w1,
                             const float* __restrict__ w2,
                             const float* __restrict__ w3) {
    int gid = blockIdx.x * 256 + threadIdx.x;           // 0..49151
    int kc   = gid & 3;
    int lane = (gid >> 2) & 31;
    int nb   = (gid >> 7) & 7;
    int t    = (gid >> 10) & 15;
    int br   = gid >> 14;
    const float* w = (br == 0 ? w1 : (br == 1 ? w2 : w3)) + t * 4096;
    int k  = nb * 8 + (lane >> 2);
    int cb = kc * 16 + 2 * (lane & 3);
    __half h0 = __float2half(w[(cb)     * 64 + k]);
    __half h1 = __float2half(w[(cb + 1) * 64 + k]);
    __half h2 = __float2half(w[(cb + 8) * 64 + k]);
    __half h3 = __float2half(w[(cb + 9) * 64 + k]);
    U32 lo = ((U32)__half_as_ushort(h1) << 16) | __half_as_ushort(h0);
    U32 hi = ((U32)__half_as_ushort(h3) << 16) | __half_as_ushort(h2);
    g_bfrag[gid] = (U64)lo | ((U64)hi << 32);
}

// ---------------- main kernel ----------------
__global__ __launch_bounds__(256, 2)
void iwht_mma_kernel(const float* __restrict__ tr1, const float* __restrict__ tr2,
                     const float* __restrict__ tr3,
                     const float* __restrict__ b1, const float* __restrict__ b2,
                     const float* __restrict__ b3,
                     float* __restrict__ out) {
    __shared__ __align__(16) char asm_buf[SMEM_SZ];

    const int tid  = threadIdx.x;
    const int lane = tid & 31;
    const int w    = tid >> 5;     // 0..7
    const int v    = w & 3;        // WHT column group
    const int h4   = (w >> 2) * 4; // n-quarter base (nbq_g = h4 + nbq)

    const int branch = blockIdx.y;
    const float* tr   = (branch == 0 ? tr1 : (branch == 1 ? tr2 : tr3));
    const float* bias = (branch == 0 ? b1  : (branch == 1 ? b2  : b3));
    const int pix0 = blockIdx.x * PIX_CTA;

    // staging role: thread -> (row 0..15, 4 floats at cseg*4)
    const int crow = tid >> 4, cseg = tid & 15;
    const float* xrow = tr + (size_t)(pix0 + crow) * 64 + cseg * 4;

    auto cvtStore = [&](float4 a, int slot) {
        __half2 h0 = __floats2half2_rn(a.x, a.y);
        __half2 h1 = __floats2half2_rn(a.z, a.w);
        *(uint2*)(asm_buf + slot * A_BUF + crow * A_PITCH + cseg * 8) =
            make_uint2(*reinterpret_cast<U32*>(&h0), *reinterpret_cast<U32*>(&h1));
    };

    // prologue: stage window 0 (t = 0..3)
    {
        float4 va[4];
        #pragma unroll
        for (int j = 0; j < 4; j++)
            va[j] = *(const float4*)(xrow + (size_t)j * T_STRIDE);
        #pragma unroll
        for (int j = 0; j < 4; j++) cvtStore(va[j], j);
    }

    const U32 sbase = smem_u32(asm_buf);
    const U32 arow0 = sbase + (U32)((lane & 15) * A_PITCH + (lane >> 4) * 16);
    const U64* gbase = g_bfrag + (size_t)branch * 16 * 8 * 32 * 4;

    auto loadB8 = [&](int t, int nbq, U32* dst) {
        const uint4* bp = (const uint4*)(gbase +
            (((size_t)t * 8 + h4 + nbq) * 32 + lane) * 4);
        uint4 a = bp[0], b = bp[1];
        dst[0] = a.x; dst[1] = a.y; dst[2] = a.z; dst[3] = a.w;
        dst[4] = b.x; dst[5] = b.y; dst[6] = b.z; dst[7] = b.w;
    };

    U32 bbuf[2][8];
    loadB8(v, 0, bbuf[0]);                  // B(u=0, nbq=0)
    __syncthreads();

    float acc[4][4][4];            // [u][nbq][i] -- all STATIC indexing
    #pragma unroll
    for (int u = 0; u < 4; u++)
        #pragma unroll
        for (int n = 0; n < 4; n++)
            #pragma unroll
            for (int i = 0; i < 4; i++) acc[u][n][i] = 0.0f;

    #pragma unroll
    for (int u = 0; u < 4; u++) {
        // prefetch next window's x (full window of slack)
        float4 pa[4];
        if (u < 3) {
            #pragma unroll
            for (int j = 0; j < 4; j++)
                pa[j] = *(const float4*)(xrow + (size_t)(4 * u + 4 + j) * T_STRIDE);
        }

        // this warp's t in this window
        const int t = 4 * u + v;
        const U32 ab = arow0 + (U32)(((u & 1) * 4 + v) * A_BUF);
        U32 af[4][4];
        #pragma unroll
        for (int kc = 0; kc < 4; kc++)
            ldm4(af[kc][0], af[kc][1], af[kc][2], af[kc][3], ab + kc * 32);

        #pragma unroll
        for (int nbq = 0; nbq < 4; nbq++) {
            // one-deep B pipeline: load next chunk before this chunk's MMAs
            if (nbq < 3)      loadB8(t, nbq + 1, bbuf[(nbq + 1) & 1]);
            else if (u < 3)   loadB8(4 * (u + 1) + v, 0, bbuf[0]);
            #pragma unroll
            for (int kc = 0; kc < 4; kc++)
                mma16816(acc[u][nbq], af[kc][0], af[kc][1], af[kc][2], af[kc][3],
                         bbuf[nbq & 1][kc * 2], bbuf[nbq & 1][kc * 2 + 1]);
        }

        // stage next window
        if (u < 3) {
            #pragma unroll
            for (int j = 0; j < 4; j++)
                cvtStore(pa[j], ((u + 1) & 1) * 4 + j);
        }
        __syncthreads();
    }
    // final barrier above also orders the last ldmatrix before ubuf overwrite

    // ---------------- epilogue: single-pass fragment exchange ----------------
    // ubuf: [nbq_g 0..7 (stride 8256B)][plane_slot p*4+v (0..15)][wlane] float4
    float* const outB = out + (size_t)branch * OPB;
    const float2 bvv = *(const float2*)(bias + 2 * lane);

    // output addressing (pix = w + 8r, k = 2*lane)
    size_t obase[2];
    #pragma unroll
    for (int r = 0; r < 2; r++) {
        const int P = pix0 + w + 8 * r;
        const int pb_ = P / 784, rr = P - pb_ * 784;
        const int ii = rr / 28, jj = rr - ii * 28;
        obase[r] = ((size_t)(pb_ * 112 + ii * 4) * 112 + jj * 4) * 64 + 2 * lane;
    }

    // writer: u-butterfly, all 4 planes, STS.128 in fragment layout
    #pragma unroll
    for (int nbq = 0; nbq < 4; nbq++) {
        float P0[4], P1[4], P2[4], P3[4];
        #pragma unroll
        for (int i = 0; i < 4; i++) {
            float y0 = acc[0][nbq][i], y1 = acc[1][nbq][i];
            float y2 = acc[2][nbq][i], y3 = acc[3][nbq][i];
            float s0 = y0 + y2, s1 = y1 + y3;
            float d0 = y0 - y2, d1 = y1 - y3;
            P0[i] = s0 + s1; P1[i] = s0 - s1;
            P2[i] = d0 + d1; P3[i] = d0 - d1;
        }
        char* nb_base = asm_buf + (h4 + nbq) * NBQ_STRIDE + lane * 16;
        *(float4*)(nb_base + ((0 * 4 + v) * 32) * 16) = make_float4(P0[0], P0[1], P0[2], P0[3]);
        *(float4*)(nb_base + ((1 * 4 + v) * 32) * 16) = make_float4(P1[0], P1[1], P1[2], P1[3]);
        *(float4*)(nb_base + ((2 * 4 + v) * 32) * 16) = make_float4(P2[0], P2[1], P2[2], P2[3]);
        *(float4*)(nb_base + ((3 * 4 + v) * 32) * 16) = make_float4(P3[0], P3[1], P3[2], P3[3]);
    }
    __syncthreads();

    // reader: nbq_g = lane>>2, gather wlane = w*4 + (lane&3); 16 indep LDS.128
    const char* rb = asm_buf + (lane >> 2) * NBQ_STRIDE + (w * 4 + (lane & 3)) * 16;
    #pragma unroll
    for (int p = 0; p < 4; p++) {
        float4 Uv[4];
        #pragma unroll
        for (int vv = 0; vv < 4; vv++)
            Uv[vv] = *(const float4*)(rb + ((p * 4 + vv) * 32) * 16);
        float4 s0, s1, d0, d1, Z[4];
        s0.x = Uv[0].x + Uv[2].x; s0.y = Uv[0].y + Uv[2].y;
        s0.z = Uv[0].z + Uv[2].z; s0.w = Uv[0].w + Uv[2].w;
        s1.x = Uv[1].x + Uv[3].x; s1.y = Uv[1].y + Uv[3].y;
        s1.z = Uv[1].z + Uv[3].z; s1.w = Uv[1].w + Uv[3].w;
        d0.x = Uv[0].x - Uv[2].x; d0.y = Uv[0].y - Uv[2].y;
        d0.z = Uv[0].z - Uv[2].z; d0.w = Uv[0].w - Uv[2].w;
        d1.x = Uv[1].x - Uv[3].x; d1.y = Uv[1].y - Uv[3].y;
        d1.z = Uv[1].z - Uv[3].z; d1.w = Uv[1].w - Uv[3].w;
        Z[0].x = s0.x + s1.x; Z[0].y = s0.y + s1.y; Z[0].z = s0.z + s1.z; Z[0].w = s0.w + s1.w;
        Z[1].x = s0.x - s1.x; Z[1].y = s0.y - s1.y; Z[1].z = s0.z - s1.z; Z[1].w = s0.w - s1.w;
        Z[2].x = d0.x + d1.x; Z[2].y = d0.y + d1.y; Z[2].z = d0.z + d1.z; Z[2].w = d0.w + d1.w;
        Z[3].x = d0.x - d1.x; Z[3].y = d0.y - d1.y; Z[3].z = d0.z - d1.z; Z[3].w = d0.w - d1.w;

        float* orow0 = outB + obase[0] + (size_t)p * 7168;   // pix = w
        float* orow1 = outB + obase[1] + (size_t)p * 7168;   // pix = w+8
        #pragma unroll
        for (int q = 0; q < 4; q++) {
            *(float2*)(orow0 + q * 64) =
                make_float2(fmaf(Z[q].x, 0.0625f, bvv.x),
                            fmaf(Z[q].y, 0.0625f, bvv.y));
            *(float2*)(orow1 + q * 64) =
                make_float2(fmaf(Z[q].z, 0.0625f, bvv.x),
                            fmaf(Z[q].w, 0.0625f, bvv.y));
        }
    }
}

// ---------------- launch ----------------
extern "C" void kernel_launch(void* const* d_in, const int* in_sizes, int n_in,
                              void* d_out, int out_size) {
    (void)in_sizes; (void)n_in; (void)out_size;
    const float* tr1 = (const float*)d_in[0];
    const float* tr2 = (const float*)d_in[1];
    const float* tr3 = (const float*)d_in[2];
    const float* w1  = (const float*)d_in[3];
    const float* w2  = (const float*)d_in[4];
    const float* w3  = (const float*)d_in[5];
    const float* b1  = (const float*)d_in[6];
    const float* b2  = (const float*)d_in[7];
    const float* b3  = (const float*)d_in[8];
    float* out = (float*)d_out;

    wprep_kernel<<<192, 256>>>(w1, w2, w3);
    dim3 grid(NBLK, 3);
    iwht_mma_kernel<<<grid, 256>>>(tr1, tr2, tr3, b1, b2, b3, out);
}

// round 17
// speedup vs baseline: 1.3385x; 1.0742x over previous
#include <cuda_runtime.h>
#include <cuda_fp16.h>
#include <cstdint>

// ---------------------------------------------------------------------------
// IWHT3Layer, round 17: round-16 + kc-outer MMA (4x longer acc RAW distance),
// af double-buffer, kc-major B fragments (dense LDG.128, 1-deep pipeline).
//   CTA: 256 threads / 8 warps / 16 pixels x 64 k x 1 branch, 2 CTAs/SM.
//   Warp (v=w&3, h=w>>2): t=4u+v, n32, acc[u][nbq][4] (static).
//   Epilogue: single-pass fragment exchange (round 16), unchanged.
// ---------------------------------------------------------------------------

#define U32 unsigned int
#define U64 unsigned long long

static constexpr int PIXELS   = 12544;
static constexpr int PIX_CTA  = 16;
static constexpr int NBLK     = PIXELS / PIX_CTA;   // 784
static constexpr int T_STRIDE = PIXELS * 64;
static constexpr long long OPB = 16LL * 112 * 112 * 64;

static constexpr int A_PITCH  = 144;                 // conflict-free ldmatrix+STS
static constexpr int A_BUF    = 16 * A_PITCH;        // 2304 B per t-slot
// staging: 8 slots = 18432 B (overlaid on ubuf)
static constexpr int NBQ_STRIDE = 16 * 512 + 64;     // 8256 B (bank-rotating)
static constexpr int SMEM_SZ  = 8 * NBQ_STRIDE;      // 66048 B

// B fragments, kc-major dense banks:
//   u64 idx = (((((br*16+t)*2 + h)*4 + kc)*2 + j)*32 + lane)*2 + (nbq&1),
//   j = nbq>>1.  Each (t,h,kc,j) bank = 512B dense -> LDG.128 at 4 wf.
__device__ __align__(16) U64 g_bfrag[3 * 16 * 2 * 4 * 2 * 32 * 2];   // 49152 u64

// ---------------- helpers ----------------
__device__ __forceinline__ U32 smem_u32(const void* p) {
    U32 a; asm("{ .reg .u64 t; cvta.to.shared.u64 t, %1; cvt.u32.u64 %0, t; }"
               : "=r"(a) : "l"(p)); return a;
}
__device__ __forceinline__ void ldm4(U32* a, U32 addr) {
    asm volatile("ldmatrix.sync.aligned.m8n8.x4.shared.b16 {%0,%1,%2,%3}, [%4];"
                 : "=r"(a[0]), "=r"(a[1]), "=r"(a[2]), "=r"(a[3]) : "r"(addr));
}
__device__ __forceinline__ void mma16816(float* d, const U32* a, U32 b0, U32 b1) {
    asm volatile("mma.sync.aligned.m16n8k16.row.col.f32.f16.f16.f32 "
                 "{%0,%1,%2,%3}, {%4,%5,%6,%7}, {%8,%9}, {%0,%1,%2,%3};"
                 : "+f"(d[0]), "+f"(d[1]), "+f"(d[2]), "+f"(d[3])
                 : "r"(a[0]), "r"(a[1]), "r"(a[2]), "r"(a[3]), "r"(b0), "r"(b1));
}

// ---------------- prep: kc-major fragment repack (coalesced stores) --------
__global__ void wprep_kernel(const float* __restrict__ w1,
                             const float* __restrict__ w2,
                             const float* __restrict__ w3) {
    int gid = blockIdx.x * 256 + threadIdx.x;           // 0..49151
    int nlo  = gid & 1;                // nbq & 1
    int lane = (gid >> 1) & 31;
    int j    = (gid >> 6) & 1;         // nbq >> 1
    int kc   = (gid >> 7) & 3;
    int h    = (gid >> 9) & 1;
    int t    = (gid >> 10) & 15;
    int br   = gid >> 14;
    int nbq  = j * 2 + nlo;
    const float* w = (br == 0 ? w1 : (br == 1 ? w2 : w3)) + t * 4096;
    int k  = (h * 4 + nbq) * 8 + (lane >> 2);
    int cb = kc * 16 + 2 * (lane & 3);
    __half h0 = __float2half(w[(cb)     * 64 + k]);
    __half h1 = __float2half(w[(cb + 1) * 64 + k]);
    __half h2 = __float2half(w[(cb + 8) * 64 + k]);
    __half h3 = __float2half(w[(cb + 9) * 64 + k]);
    U32 lo = ((U32)__half_as_ushort(h1) << 16) | __half_as_ushort(h0);
    U32 hi = ((U32)__half_as_ushort(h3) << 16) | __half_as_ushort(h2);
    g_bfrag[gid] = (U64)lo | ((U64)hi << 32);
}

// ---------------- main kernel ----------------
__global__ __launch_bounds__(256, 2)
void iwht_mma_kernel(const float* __restrict__ tr1, const float* __restrict__ tr2,
                     const float* __restrict__ tr3,
                     const float* __restrict__ b1, const float* __restrict__ b2,
                     const float* __restrict__ b3,
                     float* __restrict__ out) {
    __shared__ __align__(16) char asm_buf[SMEM_SZ];

    const int tid  = threadIdx.x;
    const int lane = tid & 31;
    const int w    = tid >> 5;     // 0..7
    const int v    = w & 3;        // WHT column group
    const int hh   = w >> 2;       // n-half
    const int h4   = hh * 4;       // nbq_g base

    const int branch = blockIdx.y;
    const float* tr   = (branch == 0 ? tr1 : (branch == 1 ? tr2 : tr3));
    const float* bias = (branch == 0 ? b1  : (branch == 1 ? b2  : b3));
    const int pix0 = blockIdx.x * PIX_CTA;

    // staging role: thread -> (row 0..15, 4 floats at cseg*4)
    const int crow = tid >> 4, cseg = tid & 15;
    const float* xrow = tr + (size_t)(pix0 + crow) * 64 + cseg * 4;

    auto cvtStore = [&](float4 a, int slot) {
        __half2 h0 = __floats2half2_rn(a.x, a.y);
        __half2 h1 = __floats2half2_rn(a.z, a.w);
        *(uint2*)(asm_buf + slot * A_BUF + crow * A_PITCH + cseg * 8) =
            make_uint2(*reinterpret_cast<U32*>(&h0), *reinterpret_cast<U32*>(&h1));
    };

    // prologue: stage window 0 (t = 0..3)
    {
        float4 va[4];
        #pragma unroll
        for (int j = 0; j < 4; j++)
            va[j] = *(const float4*)(xrow + (size_t)j * T_STRIDE);
        #pragma unroll
        for (int j = 0; j < 4; j++) cvtStore(va[j], j);
    }

    const U32 sbase = smem_u32(asm_buf);
    const U32 arow0 = sbase + (U32)((lane & 15) * A_PITCH + (lane >> 4) * 16);
    // kc-major B base for this (branch, h): uint4 units
    const uint4* gb4 = (const uint4*)g_bfrag + (size_t)branch * 16 * 2 * 4 * 2 * 32;

    // load B(t, kc): 2 dense LDG.128 -> bb[8] = {nbq0 b0,b1, nbq1 b0,b1, ...}
    auto loadBkc = [&](int t, int kc, U32* dst) {
        const uint4* p = gb4 + (((size_t)t * 2 + hh) * 4 + kc) * 2 * 32 + lane;
        uint4 a = p[0];          // j=0: nbq 0,1
        uint4 b = p[32];         // j=1: nbq 2,3
        dst[0] = a.x; dst[1] = a.y; dst[2] = a.z; dst[3] = a.w;
        dst[4] = b.x; dst[5] = b.y; dst[6] = b.z; dst[7] = b.w;
    };

    U32 bbuf[2][8];
    loadBkc(v, 0, bbuf[0]);                 // B(u=0, kc=0)
    __syncthreads();

    float acc[4][4][4];            // [u][nbq][i] -- all STATIC indexing
    #pragma unroll
    for (int u = 0; u < 4; u++)
        #pragma unroll
        for (int n = 0; n < 4; n++)
            #pragma unroll
            for (int i = 0; i < 4; i++) acc[u][n][i] = 0.0f;

    #pragma unroll
    for (int u = 0; u < 4; u++) {
        // prefetch next window's x (full window of slack)
        float4 pa[4];
        if (u < 3) {
            #pragma unroll
            for (int j = 0; j < 4; j++)
                pa[j] = *(const float4*)(xrow + (size_t)(4 * u + 4 + j) * T_STRIDE);
        }

        const int t = 4 * u + v;
        const U32 ab = arow0 + (U32)(((u & 1) * 4 + v) * A_BUF);

        U32 afb[2][4];
        ldm4(afb[0], ab);                   // kc=0

        #pragma unroll
        for (int kc = 0; kc < 4; kc++) {
            // pipeline: next kc's A-fragments and B before this kc's MMAs
            if (kc < 3) {
                ldm4(afb[(kc + 1) & 1], ab + (kc + 1) * 32);
                loadBkc(t, kc + 1, bbuf[(kc + 1) & 1]);
            } else if (u < 3) {
                loadBkc(4 * (u + 1) + v, 0, bbuf[0]);
            }
            // 4 independent MMAs (different accumulators) -> RAW distance 4
            #pragma unroll
            for (int nbq = 0; nbq < 4; nbq++)
                mma16816(acc[u][nbq], afb[kc & 1],
                         bbuf[kc & 1][nbq * 2], bbuf[kc & 1][nbq * 2 + 1]);
        }

        // stage next window
        if (u < 3) {
            #pragma unroll
            for (int j = 0; j < 4; j++)
                cvtStore(pa[j], ((u + 1) & 1) * 4 + j);
        }
        __syncthreads();
    }

    // ---------------- epilogue: single-pass fragment exchange ----------------
    float* const outB = out + (size_t)branch * OPB;
    const float2 bvv = *(const float2*)(bias + 2 * lane);

    size_t obase[2];
    #pragma unroll
    for (int r = 0; r < 2; r++) {
        const int P = pix0 + w + 8 * r;
        const int pb_ = P / 784, rr = P - pb_ * 784;
        const int ii = rr / 28, jj = rr - ii * 28;
        obase[r] = ((size_t)(pb_ * 112 + ii * 4) * 112 + jj * 4) * 64 + 2 * lane;
    }

    // writer: u-butterfly, all 4 planes, STS.128 in fragment layout
    #pragma unroll
    for (int nbq = 0; nbq < 4; nbq++) {
        float P0[4], P1[4], P2[4], P3[4];
        #pragma unroll
        for (int i = 0; i < 4; i++) {
            float y0 = acc[0][nbq][i], y1 = acc[1][nbq][i];
            float y2 = acc[2][nbq][i], y3 = acc[3][nbq][i];
            float s0 = y0 + y2, s1 = y1 + y3;
            float d0 = y0 - y2, d1 = y1 - y3;
            P0[i] = s0 + s1; P1[i] = s0 - s1;
            P2[i] = d0 + d1; P3[i] = d0 - d1;
        }
        char* nb_base = asm_buf + (h4 + nbq) * NBQ_STRIDE + lane * 16;
        *(float4*)(nb_base + ((0 * 4 + v) * 32) * 16) = make_float4(P0[0], P0[1], P0[2], P0[3]);
        *(float4*)(nb_base + ((1 * 4 + v) * 32) * 16) = make_float4(P1[0], P1[1], P1[2], P1[3]);
        *(float4*)(nb_base + ((2 * 4 + v) * 32) * 16) = make_float4(P2[0], P2[1], P2[2], P2[3]);
        *(float4*)(nb_base + ((3 * 4 + v) * 32) * 16) = make_float4(P3[0], P3[1], P3[2], P3[3]);
    }
    __syncthreads();

    // reader: nbq_g = lane>>2, gather wlane = w*4 + (lane&3); 16 indep LDS.128
    const char* rb = asm_buf + (lane >> 2) * NBQ_STRIDE + (w * 4 + (lane & 3)) * 16;
    #pragma unroll
    for (int p = 0; p < 4; p++) {
        float4 Uv[4];
        #pragma unroll
        for (int vv = 0; vv < 4; vv++)
            Uv[vv] = *(const float4*)(rb + ((p * 4 + vv) * 32) * 16);
        float4 s0, s1, d0, d1, Z[4];
        s0.x = Uv[0].x + Uv[2].x; s0.y = Uv[0].y + Uv[2].y;
        s0.z = Uv[0].z + Uv[2].z; s0.w = Uv[0].w + Uv[2].w;
        s1.x = Uv[1].x + Uv[3].x; s1.y = Uv[1].y + Uv[3].y;
        s1.z = Uv[1].z + Uv[3].z; s1.w = Uv[1].w + Uv[3].w;
        d0.x = Uv[0].x - Uv[2].x; d0.y = Uv[0].y - Uv[2].y;
        d0.z = Uv[0].z - Uv[2].z; d0.w = Uv[0].w - Uv[2].w;
        d1.x = Uv[1].x - Uv[3].x; d1.y = Uv[1].y - Uv[3].y;
        d1.z = Uv[1].z - Uv[3].z; d1.w = Uv[1].w - Uv[3].w;
        Z[0].x = s0.x + s1.x; Z[0].y = s0.y + s1.y; Z[0].z = s0.z + s1.z; Z[0].w = s0.w + s1.w;
        Z[1].x = s0.x - s1.x; Z[1].y = s0.y - s1.y; Z[1].z = s0.z - s1.z; Z[1].w = s0.w - s1.w;
        Z[2].x = d0.x + d1.x; Z[2].y = d0.y + d1.y; Z[2].z = d0.z + d1.z; Z[2].w = d0.w + d1.w;
        Z[3].x = d0.x - d1.x; Z[3].y = d0.y - d1.y; Z[3].z = d0.z - d1.z; Z[3].w = d0.w - d1.w;

        float* orow0 = outB + obase[0] + (size_t)p * 7168;   // pix = w
        float* orow1 = outB + obase[1] + (size_t)p * 7168;   // pix = w+8
        #pragma unroll
        for (int q = 0; q < 4; q++) {
            *(float2*)(orow0 + q * 64) =
                make_float2(fmaf(Z[q].x, 0.0625f, bvv.x),
                            fmaf(Z[q].y, 0.0625f, bvv.y));
            *(float2*)(orow1 + q * 64) =
                make_float2(fmaf(Z[q].z, 0.0625f, bvv.x),
                            fmaf(Z[q].w, 0.0625f, bvv.y));
        }
    }
}

// ---------------- launch ----------------
extern "C" void kernel_launch(void* const* d_in, const int* in_sizes, int n_in,
                              void* d_out, int out_size) {
    (void)in_sizes; (void)n_in; (void)out_size;
    const float* tr1 = (const float*)d_in[0];
    const float* tr2 = (const float*)d_in[1];
    const float* tr3 = (const float*)d_in[2];
    const float* w1  = (const float*)d_in[3];
    const float* w2  = (const float*)d_in[4];
    const float* w3  = (const float*)d_in[5];
    const float* b1  = (const float*)d_in[6];
    const float* b2  = (const float*)d_in[7];
    const float* b3  = (const float*)d_in[8];
    float* out = (float*)d_out;

    wprep_kernel<<<192, 256>>>(w1, w2, w3);
    dim3 grid(NBLK, 3);
    iwht_mma_kernel<<<grid, 256>>>(tr1, tr2, tr3, b1, b2, b3, out);
}